// round 12
// baseline (speedup 1.0000x reference)
#include <cuda_runtime.h>
#include <cuda_fp16.h>
#include <cstdint>
#include <cstddef>

#define C_IN    128
#define C_OUT   256
#define HWD     64
#define KDIM    1152                  // 9 taps * 128 ch, k = tap*128 + c
#define M_TOTAL 65536
#define KC      64                    // K per stage (half a tap)
#define KITER   (KDIM / KC)           // 18
#define STAGES  3

#define A_ST    (256 * 128)           // 32KB A per stage
#define B_ST    (128 * 128)           // 16KB B per stage
#define STAGE_B (A_ST + B_ST)         // 48KB
#define SMEM_TOTAL (STAGES * STAGE_B) // 147456

// ---------------- scratch ----------------
__device__ __half g_xh[(size_t)M_TOTAL * C_IN];   // x in NHWC fp16
__device__ __half g_Bt[(size_t)C_OUT * KDIM];     // fused weights [oc][tap*128+c]

// ---------------- helpers ----------------
__device__ __forceinline__ uint32_t smem_u32(const void* p) {
    uint32_t a;
    asm("{ .reg .u64 t; cvta.to.shared.u64 t, %1; cvt.u32.u64 %0, t; }" : "=r"(a) : "l"(p));
    return a;
}
__device__ __forceinline__ void cpasync16(uint32_t dst, const void* src) {
    asm volatile("cp.async.cg.shared.global [%0], [%1], 16;" :: "r"(dst), "l"(src) : "memory");
}
__device__ __forceinline__ void cpasync16z(uint32_t dst, const void* src, uint32_t src_sz) {
    asm volatile("cp.async.cg.shared.global [%0], [%1], 16, %2;"
                 :: "r"(dst), "l"(src), "r"(src_sz) : "memory");
}
__device__ __forceinline__ void cp_commit() { asm volatile("cp.async.commit_group;" ::: "memory"); }
__device__ __forceinline__ void cp_wait1()  { asm volatile("cp.async.wait_group 1;" ::: "memory"); }
__device__ __forceinline__ void cp_wait0()  { asm volatile("cp.async.wait_group 0;" ::: "memory"); }

__device__ __forceinline__ void ldsm4(uint32_t* r, uint32_t addr) {
    asm volatile("ldmatrix.sync.aligned.m8n8.x4.shared.b16 {%0,%1,%2,%3}, [%4];"
                 : "=r"(r[0]), "=r"(r[1]), "=r"(r[2]), "=r"(r[3]) : "r"(addr));
}
__device__ __forceinline__ void mma16816(float* d, const uint32_t* a, const uint32_t* b) {
    asm volatile(
        "mma.sync.aligned.m16n8k16.row.col.f32.f16.f16.f32 "
        "{%0,%1,%2,%3}, {%4,%5,%6,%7}, {%8,%9}, {%0,%1,%2,%3};"
        : "+f"(d[0]), "+f"(d[1]), "+f"(d[2]), "+f"(d[3])
        : "r"(a[0]), "r"(a[1]), "r"(a[2]), "r"(a[3]), "r"(b[0]), "r"(b[1]));
}

// ---------------------------------------------------------------------------
// Kernel 1 (merged prologue): transpose + weight fusion
// ---------------------------------------------------------------------------
__global__ __launch_bounds__(256)
void prologue_kernel(const float* __restrict__ x,
                     const float* __restrict__ W,
                     const float* __restrict__ lA,
                     const float* __restrict__ lB) {
    const int tid = threadIdx.x;
    if (blockIdx.x < 1024) {
        __shared__ float sT[128][65];
        const int n = blockIdx.x >> 6;
        const int h = blockIdx.x & 63;
        const float* xp = x + ((size_t)n * C_IN * HWD + h) * HWD;
#pragma unroll
        for (int i = 0; i < 32; ++i) {
            int idx = i * 256 + tid;
            int c = idx >> 6, w = idx & 63;
            sT[c][w] = xp[(size_t)c * (HWD * HWD) + w];
        }
        __syncthreads();
        __half* dst = g_xh + ((size_t)(n * 64 + h) * 64) * C_IN;
#pragma unroll
        for (int i = 0; i < 16; ++i) {
            int idx = i * 256 + tid;
            int w = idx >> 6, c = (idx & 63) * 2;
            __half2 v = __floats2half2_rn(sT[c][w], sT[c + 1][w]);
            *(__half2*)(dst + (size_t)w * C_IN + c) = v;
        }
    } else {
        int idx = (blockIdx.x - 1024) * 256 + tid;   // oc*1152 + c*9 + tap
        int oc  = idx / KDIM;
        int rem = idx - oc * KDIM;
        int c   = rem / 9;
        int tap = rem - c * 9;
        float s = 0.f;
#pragma unroll
        for (int r = 0; r < 8; ++r)
            s += lB[oc * 8 + r] * lA[r * KDIM + rem];
        g_Bt[(size_t)oc * KDIM + tap * 128 + c] = __float2half_rn(W[idx] + 2.0f * s);
    }
}

// ---------------------------------------------------------------------------
// Kernel 2: implicit-conv GEMM. CTA 256m x 128oc, warps 64x64, XOR swizzle.
// ---------------------------------------------------------------------------
__device__ __forceinline__ void load_stage(uint32_t sm, int it, int m0, int oc0, int tid) {
    const uint32_t st = (uint32_t)(it % STAGES) * STAGE_B;
    const int tap = it >> 1;
    const int c0  = (it & 1) * 64;
    const int kh  = tap / 3;
    const int kw  = tap - kh * 3;
    const int n   = m0 >> 12;
    const int h0  = (m0 >> 6) & 63;

    // A: 256 m-rows x 128B; 2048 chunks / 256 thr = 8 each
#pragma unroll
    for (int i = 0; i < 8; ++i) {
        int idx = tid + i * 256;
        int r   = idx >> 3;                    // 0..255
        int q   = idx & 7;
        int hh  = h0 + (r >> 6) + kh - 1;
        int ww  = (r & 63) + kw - 1;
        bool ok = ((unsigned)hh < 64u) && ((unsigned)ww < 64u);
        const __half* src = ok
            ? &g_xh[(size_t)(((n * 64 + hh) * 64) + ww) * C_IN + c0 + q * 8]
            : &g_xh[0];
        cpasync16z(sm + st + r * 128 + ((q ^ (r & 7)) * 16), src, ok ? 16u : 0u);
    }
    // B: 128 oc-rows x 128B; 1024 chunks / 256 = 4 each
#pragma unroll
    for (int i = 0; i < 4; ++i) {
        int idx = tid + i * 256;
        int r   = idx >> 3;
        int q   = idx & 7;
        cpasync16(sm + st + A_ST + r * 128 + ((q ^ (r & 7)) * 16),
                  &g_Bt[(size_t)(oc0 + r) * KDIM + tap * 128 + c0 + q * 8]);
    }
    cp_commit();
}

__global__ __launch_bounds__(256, 1)
void gemm_kernel(const float* __restrict__ bias, float* __restrict__ out) {
    extern __shared__ __align__(16) char smem[];
    const uint32_t sm = smem_u32(smem);

    const int tid  = threadIdx.x;
    const int wid  = tid >> 5;
    const int lane = tid & 31;
    const int oc0  = blockIdx.x * 128;
    const int m0   = blockIdx.y * 256;

    const int wm  = wid & 3;               // 4 m-warps (64 m each)
    const int wn  = wid >> 2;              // 2 n-warps (64 oc each)
    const int grp = lane >> 3;
    const int l7  = lane & 7;
    const int hi  = lane >> 4;

    uint32_t aAddr[4], bAddr[4], cA[4], cB[4];
#pragma unroll
    for (int i = 0; i < 4; ++i)
        aAddr[i] = sm + (uint32_t)(wm * 64 + i * 16 + (lane & 15)) * 128;
#pragma unroll
    for (int h = 0; h < 4; ++h)
        bAddr[h] = sm + A_ST + (uint32_t)(wn * 64 + h * 16 + (grp >> 1) * 8 + l7) * 128;
#pragma unroll
    for (int ks = 0; ks < 4; ++ks) {
        cA[ks] = (uint32_t)(((ks * 2 + hi) ^ l7) * 16);
        cB[ks] = (uint32_t)(((ks * 2 + (grp & 1)) ^ l7) * 16);
    }

    float acc[4][8][4];
#pragma unroll
    for (int i = 0; i < 4; ++i)
#pragma unroll
        for (int j = 0; j < 8; ++j)
#pragma unroll
            for (int p = 0; p < 4; ++p) acc[i][j][p] = 0.f;

    load_stage(sm, 0, m0, oc0, tid);
    load_stage(sm, 1, m0, oc0, tid);
    cp_wait1();
    __syncthreads();

    uint32_t aR[4], aN[4], bF[2][8][2];
    {   // prime: B(it0,ks0) 4 ldsm, A(it0,ks0,i0)
        uint32_t r[4];
#pragma unroll
        for (int h = 0; h < 4; ++h) {
            ldsm4(r, bAddr[h] + cB[0]);
            bF[0][2*h][0]=r[0]; bF[0][2*h][1]=r[1]; bF[0][2*h+1][0]=r[2]; bF[0][2*h+1][1]=r[3];
        }
        ldsm4(aR, aAddr[0] + cA[0]);
    }

    for (int it = 0; it < KITER; ++it) {
        const uint32_t sb  = (uint32_t)(it % STAGES) * STAGE_B;
        const uint32_t sbN = (uint32_t)((it + 1) % STAGES) * STAGE_B;
        if (it + 2 < KITER) load_stage(sm, it + 2, m0, oc0, tid);

#pragma unroll
        for (int ks = 0; ks < 4; ++ks) {
            const int cur = ks & 1;
            const int nxt = cur ^ 1;
            uint32_t (*bR)[2] = bF[cur];
            uint32_t r[4];

            ldsm4(aN, aAddr[1] + sb + cA[ks]);
#pragma unroll
            for (int j = 0; j < 8; ++j) mma16816(acc[0][j], aR, bR[j]);
            ldsm4(aR, aAddr[2] + sb + cA[ks]);
#pragma unroll
            for (int j = 0; j < 8; ++j) mma16816(acc[1][j], aN, bR[j]);

            if (ks < 3) {
                ldsm4(aN, aAddr[3] + sb + cA[ks]);
                ldsm4(r, bAddr[0] + sb + cB[ks + 1]);
                bF[nxt][0][0]=r[0]; bF[nxt][0][1]=r[1]; bF[nxt][1][0]=r[2]; bF[nxt][1][1]=r[3];
                ldsm4(r, bAddr[1] + sb + cB[ks + 1]);
                bF[nxt][2][0]=r[0]; bF[nxt][2][1]=r[1]; bF[nxt][3][0]=r[2]; bF[nxt][3][1]=r[3];
#pragma unroll
                for (int j = 0; j < 8; ++j) mma16816(acc[2][j], aR, bR[j]);
                ldsm4(r, bAddr[2] + sb + cB[ks + 1]);
                bF[nxt][4][0]=r[0]; bF[nxt][4][1]=r[1]; bF[nxt][5][0]=r[2]; bF[nxt][5][1]=r[3];
                ldsm4(r, bAddr[3] + sb + cB[ks + 1]);
                bF[nxt][6][0]=r[0]; bF[nxt][6][1]=r[1]; bF[nxt][7][0]=r[2]; bF[nxt][7][1]=r[3];
                ldsm4(aR, aAddr[0] + sb + cA[ks + 1]);
#pragma unroll
                for (int j = 0; j < 8; ++j) mma16816(acc[3][j], aN, bR[j]);
            } else if (it + 1 < KITER) {
                ldsm4(aN, aAddr[3] + sb + cA[ks]);
#pragma unroll
                for (int j = 0; j < 8; ++j) mma16816(acc[2][j], aR, bR[j]);
                if (it < KITER - 3) cp_wait1(); else cp_wait0();
                ldsm4(r, bAddr[0] + sbN + cB[0]);
                bF[nxt][0][0]=r[0]; bF[nxt][0][1]=r[1]; bF[nxt][1][0]=r[2]; bF[nxt][1][1]=r[3];
                ldsm4(r, bAddr[1] + sbN + cB[0]);
                bF[nxt][2][0]=r[0]; bF[nxt][2][1]=r[1]; bF[nxt][3][0]=r[2]; bF[nxt][3][1]=r[3];
                ldsm4(r, bAddr[2] + sbN + cB[0]);
                bF[nxt][4][0]=r[0]; bF[nxt][4][1]=r[1]; bF[nxt][5][0]=r[2]; bF[nxt][5][1]=r[3];
                ldsm4(r, bAddr[3] + sbN + cB[0]);
                bF[nxt][6][0]=r[0]; bF[nxt][6][1]=r[1]; bF[nxt][7][0]=r[2]; bF[nxt][7][1]=r[3];
                ldsm4(aR, aAddr[0] + sbN + cA[0]);
#pragma unroll
                for (int j = 0; j < 8; ++j) mma16816(acc[3][j], aN, bR[j]);
                __syncthreads();
            } else {
                ldsm4(aN, aAddr[3] + sb + cA[ks]);
#pragma unroll
                for (int j = 0; j < 8; ++j) mma16816(acc[2][j], aR, bR[j]);
#pragma unroll
                for (int j = 0; j < 8; ++j) mma16816(acc[3][j], aN, bR[j]);
            }
        }
    }

    // epilogue
    const int g  = lane >> 2;
    const int c2 = (lane & 3) * 2;
    const int n  = m0 >> 12;
    float bia[8][2];
#pragma unroll
    for (int j = 0; j < 8; ++j) {
        int oc = oc0 + wn * 64 + j * 8 + c2;
        bia[j][0] = __ldg(bias + oc);
        bia[j][1] = __ldg(bias + oc + 1);
    }
#pragma unroll
    for (int i = 0; i < 4; ++i) {
#pragma unroll
        for (int rr = 0; rr < 2; ++rr) {
            int m = m0 + wm * 64 + i * 16 + g + rr * 8;
            size_t base = (size_t)n * (C_OUT * 4096) + (m & 4095);
#pragma unroll
            for (int j = 0; j < 8; ++j) {
                int oc = oc0 + wn * 64 + j * 8 + c2;
                out[base + (size_t)oc * 4096]       = acc[i][j][rr * 2 + 0] + bia[j][0];
                out[base + (size_t)(oc + 1) * 4096] = acc[i][j][rr * 2 + 1] + bia[j][1];
            }
        }
    }
}

// ---------------------------------------------------------------------------
extern "C" void kernel_launch(void* const* d_in, const int* in_sizes, int n_in,
                              void* d_out, int out_size) {
    const float* x      = (const float*)d_in[0];
    const float* W      = (const float*)d_in[1];
    const float* b      = (const float*)d_in[2];
    const float* lora_A = (const float*)d_in[3];
    const float* lora_B = (const float*)d_in[4];
    float* out = (float*)d_out;

    static int smem_set = 0;
    if (!smem_set) {
        cudaFuncSetAttribute(gemm_kernel,
                             cudaFuncAttributeMaxDynamicSharedMemorySize, SMEM_TOTAL);
        smem_set = 1;
    }

    prologue_kernel<<<1024 + (C_OUT * KDIM) / 256, 256>>>(x, W, lora_A, lora_B);
    gemm_kernel<<<dim3(2, M_TOTAL / 256), 256, SMEM_TOTAL>>>(b, out);
}

// round 15
// speedup vs baseline: 1.0966x; 1.0966x over previous
#include <cuda_runtime.h>
#include <cuda_fp16.h>
#include <cstdint>
#include <cstddef>

#define C_IN    128
#define C_OUT   256
#define HWD     64
#define KDIM    1152                  // 9 taps * 128 ch, k = tap*128 + c
#define M_TOTAL 65536
#define KC      64
#define KITER   (KDIM / KC)           // 18
#define NK16    (KDIM / 16)           // 72
#define STAGES  4

#define A_ST    (128 * 128)           // 16KB per stage (A only)
#define SMEM_TOTAL (STAGES * A_ST)    // 65536 -> 2 CTAs/SM

// ---------------- scratch ----------------
__device__ __half g_xh[(size_t)M_TOTAL * C_IN];      // x in NHWC fp16
// B in mma-fragment layout: [k16][n8][lane] {b0,b1} as uint2 (590KB, L2-hot)
__device__ uint2  g_Bf[NK16 * 32 * 32];

// ---------------- helpers ----------------
__device__ __forceinline__ uint32_t smem_u32(const void* p) {
    uint32_t a;
    asm("{ .reg .u64 t; cvta.to.shared.u64 t, %1; cvt.u32.u64 %0, t; }" : "=r"(a) : "l"(p));
    return a;
}
__device__ __forceinline__ void cpasync16z(uint32_t dst, const void* src, uint32_t src_sz) {
    asm volatile("cp.async.cg.shared.global [%0], [%1], 16, %2;"
                 :: "r"(dst), "l"(src), "r"(src_sz) : "memory");
}
__device__ __forceinline__ void cp_commit() { asm volatile("cp.async.commit_group;" ::: "memory"); }
__device__ __forceinline__ void cp_wait1()  { asm volatile("cp.async.wait_group 1;" ::: "memory"); }
__device__ __forceinline__ void cp_wait0()  { asm volatile("cp.async.wait_group 0;" ::: "memory"); }

__device__ __forceinline__ void ldsm4(uint32_t* r, uint32_t addr) {
    asm volatile("ldmatrix.sync.aligned.m8n8.x4.shared.b16 {%0,%1,%2,%3}, [%4];"
                 : "=r"(r[0]), "=r"(r[1]), "=r"(r[2]), "=r"(r[3]) : "r"(addr));
}
__device__ __forceinline__ void mma16816(float* d, const uint32_t* a, const uint32_t* b) {
    asm volatile(
        "mma.sync.aligned.m16n8k16.row.col.f32.f16.f16.f32 "
        "{%0,%1,%2,%3}, {%4,%5,%6,%7}, {%8,%9}, {%0,%1,%2,%3};"
        : "+f"(d[0]), "+f"(d[1]), "+f"(d[2]), "+f"(d[3])
        : "r"(a[0]), "r"(a[1]), "r"(a[2]), "r"(a[3]), "r"(b[0]), "r"(b[1]));
}

// ---------------------------------------------------------------------------
// Kernel 1 (merged prologue): NHWC transpose + weight fusion into B-frag layout
// ---------------------------------------------------------------------------
__global__ __launch_bounds__(256)
void prologue_kernel(const float* __restrict__ x,
                     const float* __restrict__ W,
                     const float* __restrict__ lA,
                     const float* __restrict__ lB) {
    const int tid = threadIdx.x;
    if (blockIdx.x < 1024) {
        __shared__ float sT[128][65];
        const int n = blockIdx.x >> 6;
        const int h = blockIdx.x & 63;
        const float* xp = x + ((size_t)n * C_IN * HWD + h) * HWD;
#pragma unroll
        for (int i = 0; i < 32; ++i) {
            int idx = i * 256 + tid;
            int c = idx >> 6, w = idx & 63;
            sT[c][w] = xp[(size_t)c * (HWD * HWD) + w];
        }
        __syncthreads();
        __half* dst = g_xh + ((size_t)(n * 64 + h) * 64) * C_IN;
#pragma unroll
        for (int i = 0; i < 16; ++i) {
            int idx = i * 256 + tid;
            int w = idx >> 6, c = (idx & 63) * 2;
            __half2 v = __floats2half2_rn(sT[c][w], sT[c + 1][w]);
            *(__half2*)(dst + (size_t)w * C_IN + c) = v;
        }
    } else {
        int idx = (blockIdx.x - 1024) * 256 + tid;   // oc*1152 + c*9 + tap
        int oc  = idx / KDIM;
        int rem = idx - oc * KDIM;
        int c   = rem / 9;
        int tap = rem - c * 9;
        float s = 0.f;
#pragma unroll
        for (int r = 0; r < 8; ++r)
            s += lB[oc * 8 + r] * lA[r * KDIM + rem];
        __half v = __float2half_rn(W[idx] + 2.0f * s);
        // scatter into mma B-fragment layout
        int k    = tap * 128 + c;            // gemm K
        int k16  = k >> 4;
        int kin  = k & 15;
        int i    = kin >> 3;                 // b0 / b1
        int kk   = kin & 7;
        int lane = ((oc & 7) << 2) | (kk >> 1);
        int h    = kk & 1;
        __half* dst = (__half*)&g_Bf[((k16 * 32 + (oc >> 3)) * 32 + lane)];
        dst[i * 2 + h] = v;
    }
}

// ---------------------------------------------------------------------------
// Kernel 2: implicit-conv GEMM. CTA 128m x 128oc, warps 32m x 64n.
// A: smem (XOR swizzle) + ldsm.  B: direct LDG from fragment-layout global.
// ---------------------------------------------------------------------------
__device__ __forceinline__ void load_stage(uint32_t sm, int it, int m0, int tid) {
    const uint32_t st = (uint32_t)(it & 3) * A_ST;
    const int tap = it >> 1;
    const int c0  = (it & 1) * 64;
    const int kh  = tap / 3;
    const int kw  = tap - kh * 3;
    const int n   = m0 >> 12;
    const int h0  = (m0 >> 6) & 63;
#pragma unroll
    for (int i = 0; i < 4; ++i) {
        int idx = tid + i * 256;               // 0..1023
        int r   = idx >> 3;
        int q   = idx & 7;
        int hh  = h0 + (r >> 6) + kh - 1;
        int ww  = (r & 63) + kw - 1;
        bool ok = ((unsigned)hh < 64u) && ((unsigned)ww < 64u);
        const __half* src = ok
            ? &g_xh[(size_t)(((n * 64 + hh) * 64) + ww) * C_IN + c0 + q * 8]
            : &g_xh[0];
        cpasync16z(st + sm + r * 128 + ((q ^ (r & 7)) * 16), src, ok ? 16u : 0u);
    }
    cp_commit();
}

__global__ __launch_bounds__(256, 2)
void gemm_kernel(const float* __restrict__ bias, float* __restrict__ out) {
    extern __shared__ __align__(16) char smem[];
    const uint32_t sm = smem_u32(smem);

    const int tid  = threadIdx.x;
    const int wid  = tid >> 5;
    const int lane = tid & 31;
    const int oc0  = blockIdx.x * 128;
    const int m0   = blockIdx.y * 128;

    const int wm  = wid & 3;               // 4 m-warps (32 m each)
    const int wn  = wid >> 2;              // 2 n-warps (64 oc each)
    const int l7  = lane & 7;
    const int hi  = lane >> 4;

    uint32_t aAddr[2], cA[4];
#pragma unroll
    for (int i = 0; i < 2; ++i)
        aAddr[i] = sm + (uint32_t)(wm * 32 + i * 16 + (lane & 15)) * 128;
#pragma unroll
    for (int ks = 0; ks < 4; ++ks)
        cA[ks] = (uint32_t)(((ks * 2 + hi) ^ l7) * 16);

    // B fragment base: lane-resolved pointer; step per k16 = 32*32 uint2
    const uint2* bBase = g_Bf + ((oc0 >> 3) + wn * 8) * 32 + lane;

    float acc[2][8][4];
#pragma unroll
    for (int i = 0; i < 2; ++i)
#pragma unroll
        for (int j = 0; j < 8; ++j)
#pragma unroll
            for (int p = 0; p < 4; ++p) acc[i][j][p] = 0.f;

    load_stage(sm, 0, m0, tid);
    load_stage(sm, 1, m0, tid);
    cp_wait1();                       // stage 0 resident
    __syncthreads();

    uint32_t aR[4], aN[4];
    uint2 bF[2][8];
    {   // prime: B(k16=0), A(it0, ks0, i0)
#pragma unroll
        for (int j = 0; j < 8; ++j)
            bF[0][j] = __ldg(bBase + (size_t)j * 32);
        ldsm4(aR, aAddr[0] + cA[0]);
    }

    for (int it = 0; it < KITER; ++it) {
        const uint32_t sb  = (uint32_t)(it & 3) * A_ST;
        const uint32_t sbN = (uint32_t)((it + 1) & 3) * A_ST;
        if (it + 2 < KITER) load_stage(sm, it + 2, m0, tid);

#pragma unroll
        for (int ks = 0; ks < 4; ++ks) {
            const int cur = ks & 1;
            const int nxt = cur ^ 1;
            const int k16g = it * 4 + ks;
            uint2* bR = bF[cur];

            ldsm4(aN, aAddr[1] + sb + cA[ks]);

            // prefetch next k16's B frags (global index is contiguous)
            const int kn = (k16g + 1 < NK16) ? (k16g + 1) : 0;
            const uint2* bp = bBase + (size_t)kn * (32 * 32);
#pragma unroll
            for (int j = 0; j < 8; ++j)
                bF[nxt][j] = __ldg(bp + (size_t)j * 32);

#pragma unroll
            for (int j = 0; j < 8; ++j)
                mma16816(acc[0][j], aR, (const uint32_t*)&bR[j]);

            if (ks < 3) {
                ldsm4(aR, aAddr[0] + sb + cA[ks + 1]);
            } else if (it + 1 < KITER) {
                if (it + 2 < KITER) cp_wait1(); else cp_wait0();
                ldsm4(aR, aAddr[0] + sbN + cA[0]);
            }

#pragma unroll
            for (int j = 0; j < 8; ++j)
                mma16816(acc[1][j], aN, (const uint32_t*)&bR[j]);
        }
        if (it + 1 < KITER) __syncthreads();   // stage it fully read
    }

    // epilogue: warp tile 32m x 64n
    const int g  = lane >> 2;
    const int c2 = (lane & 3) * 2;
    const int n  = m0 >> 12;
    float bia[8][2];
#pragma unroll
    for (int j = 0; j < 8; ++j) {
        int oc = oc0 + wn * 64 + j * 8 + c2;
        bia[j][0] = __ldg(bias + oc);
        bia[j][1] = __ldg(bias + oc + 1);
    }
#pragma unroll
    for (int i = 0; i < 2; ++i) {
#pragma unroll
        for (int rr = 0; rr < 2; ++rr) {
            int m = m0 + wm * 32 + i * 16 + g + rr * 8;
            size_t base = (size_t)n * (C_OUT * 4096) + (m & 4095);
#pragma unroll
            for (int j = 0; j < 8; ++j) {
                int oc = oc0 + wn * 64 + j * 8 + c2;
                out[base + (size_t)oc * 4096]       = acc[i][j][rr * 2 + 0] + bia[j][0];
                out[base + (size_t)(oc + 1) * 4096] = acc[i][j][rr * 2 + 1] + bia[j][1];
            }
        }
    }
}

// ---------------------------------------------------------------------------
extern "C" void kernel_launch(void* const* d_in, const int* in_sizes, int n_in,
                              void* d_out, int out_size) {
    const float* x      = (const float*)d_in[0];
    const float* W      = (const float*)d_in[1];
    const float* b      = (const float*)d_in[2];
    const float* lora_A = (const float*)d_in[3];
    const float* lora_B = (const float*)d_in[4];
    float* out = (float*)d_out;

    static int smem_set = 0;
    if (!smem_set) {
        cudaFuncSetAttribute(gemm_kernel,
                             cudaFuncAttributeMaxDynamicSharedMemorySize, SMEM_TOTAL);
        smem_set = 1;
    }

    prologue_kernel<<<1024 + (C_OUT * KDIM) / 256, 256>>>(x, W, lora_A, lora_B);
    gemm_kernel<<<dim3(2, M_TOTAL / 128), 256, SMEM_TOTAL>>>(b, out);
}

// round 16
// speedup vs baseline: 1.1283x; 1.0289x over previous
#include <cuda_runtime.h>
#include <cuda_fp16.h>
#include <cstdint>
#include <cstddef>

#define C_IN    128
#define C_OUT   256
#define HWD     64
#define KDIM    1152                  // 9 taps * 128 ch, k = tap*128 + c
#define M_TOTAL 65536
#define KC      64
#define KITER   (KDIM / KC)           // 18
#define STAGES  3
#define NTILES  1024                  // (m/128) * (oc/128) = 512 * 2
#define GRID_P  304                   // 2 CTAs/SM * 152 SMs, persistent

#define A_ST    (128 * 128)           // 16KB
#define STAGE_B (2 * A_ST)            // A + B = 32KB
#define SMEM_TOTAL (STAGES * STAGE_B) // 98304 -> 2 CTAs/SM

// ---------------- scratch ----------------
__device__ __half g_xh[(size_t)M_TOTAL * C_IN];   // x in NHWC fp16
__device__ __half g_Bt[(size_t)C_OUT * KDIM];     // fused weights [oc][tap*128+c]

// ---------------- helpers ----------------
__device__ __forceinline__ uint32_t smem_u32(const void* p) {
    uint32_t a;
    asm("{ .reg .u64 t; cvta.to.shared.u64 t, %1; cvt.u32.u64 %0, t; }" : "=r"(a) : "l"(p));
    return a;
}
__device__ __forceinline__ void cpasync16(uint32_t dst, const void* src) {
    asm volatile("cp.async.cg.shared.global [%0], [%1], 16;" :: "r"(dst), "l"(src) : "memory");
}
__device__ __forceinline__ void cpasync16z(uint32_t dst, const void* src, uint32_t src_sz) {
    asm volatile("cp.async.cg.shared.global [%0], [%1], 16, %2;"
                 :: "r"(dst), "l"(src), "r"(src_sz) : "memory");
}
__device__ __forceinline__ void cp_commit() { asm volatile("cp.async.commit_group;" ::: "memory"); }
__device__ __forceinline__ void cp_wait1()  { asm volatile("cp.async.wait_group 1;" ::: "memory"); }
__device__ __forceinline__ void cp_wait0()  { asm volatile("cp.async.wait_group 0;" ::: "memory"); }

__device__ __forceinline__ void ldsm4(uint32_t* r, uint32_t addr) {
    asm volatile("ldmatrix.sync.aligned.m8n8.x4.shared.b16 {%0,%1,%2,%3}, [%4];"
                 : "=r"(r[0]), "=r"(r[1]), "=r"(r[2]), "=r"(r[3]) : "r"(addr));
}
__device__ __forceinline__ void mma16816(float* d, const uint32_t* a, const uint32_t* b) {
    asm volatile(
        "mma.sync.aligned.m16n8k16.row.col.f32.f16.f16.f32 "
        "{%0,%1,%2,%3}, {%4,%5,%6,%7}, {%8,%9}, {%0,%1,%2,%3};"
        : "+f"(d[0]), "+f"(d[1]), "+f"(d[2]), "+f"(d[3])
        : "r"(a[0]), "r"(a[1]), "r"(a[2]), "r"(a[3]), "r"(b[0]), "r"(b[1]));
}

// ---------------------------------------------------------------------------
// Kernel 1 (merged prologue): transpose + weight fusion
// ---------------------------------------------------------------------------
__global__ __launch_bounds__(256)
void prologue_kernel(const float* __restrict__ x,
                     const float* __restrict__ W,
                     const float* __restrict__ lA,
                     const float* __restrict__ lB) {
    const int tid = threadIdx.x;
    if (blockIdx.x < 1024) {
        __shared__ float sT[128][65];
        const int n = blockIdx.x >> 6;
        const int h = blockIdx.x & 63;
        const float* xp = x + ((size_t)n * C_IN * HWD + h) * HWD;
#pragma unroll
        for (int i = 0; i < 32; ++i) {
            int idx = i * 256 + tid;
            int c = idx >> 6, w = idx & 63;
            sT[c][w] = xp[(size_t)c * (HWD * HWD) + w];
        }
        __syncthreads();
        __half* dst = g_xh + ((size_t)(n * 64 + h) * 64) * C_IN;
#pragma unroll
        for (int i = 0; i < 16; ++i) {
            int idx = i * 256 + tid;
            int w = idx >> 6, c = (idx & 63) * 2;
            __half2 v = __floats2half2_rn(sT[c][w], sT[c + 1][w]);
            *(__half2*)(dst + (size_t)w * C_IN + c) = v;
        }
    } else {
        int idx = (blockIdx.x - 1024) * 256 + tid;   // oc*1152 + c*9 + tap
        int oc  = idx / KDIM;
        int rem = idx - oc * KDIM;
        int c   = rem / 9;
        int tap = rem - c * 9;
        float s = 0.f;
#pragma unroll
        for (int r = 0; r < 8; ++r)
            s += lB[oc * 8 + r] * lA[r * KDIM + rem];
        g_Bt[(size_t)oc * KDIM + tap * 128 + c] = __float2half_rn(W[idx] + 2.0f * s);
    }
}

// ---------------------------------------------------------------------------
// Kernel 2: persistent implicit-conv GEMM. CTA tile 128m x 128oc, KC=64.
// ---------------------------------------------------------------------------
__device__ __forceinline__ void load_stage(uint32_t sm, int it, int m0, int oc0, int tid) {
    const uint32_t st = (uint32_t)(it % STAGES) * STAGE_B;
    const int tap = it >> 1;
    const int c0  = (it & 1) * 64;
    const int kh  = tap / 3;
    const int kw  = tap - kh * 3;
    const int n   = m0 >> 12;
    const int h0  = (m0 >> 6) & 63;

#pragma unroll
    for (int i = 0; i < 4; ++i) {
        int idx = tid + i * 256;
        int r   = idx >> 3;
        int q   = idx & 7;
        int hh  = h0 + (r >> 6) + kh - 1;
        int ww  = (r & 63) + kw - 1;
        bool ok = ((unsigned)hh < 64u) && ((unsigned)ww < 64u);
        const __half* src = ok
            ? &g_xh[(size_t)(((n * 64 + hh) * 64) + ww) * C_IN + c0 + q * 8]
            : &g_xh[0];
        cpasync16z(sm + st + r * 128 + ((q ^ (r & 7)) * 16), src, ok ? 16u : 0u);
    }
#pragma unroll
    for (int i = 0; i < 4; ++i) {
        int idx = tid + i * 256;
        int r   = idx >> 3;
        int q   = idx & 7;
        cpasync16(sm + st + A_ST + r * 128 + ((q ^ (r & 7)) * 16),
                  &g_Bt[(size_t)(oc0 + r) * KDIM + tap * 128 + c0 + q * 8]);
    }
    cp_commit();
}

__global__ __launch_bounds__(256, 2)
void gemm_kernel(const float* __restrict__ bias, float* __restrict__ out) {
    extern __shared__ __align__(16) char smem[];
    const uint32_t sm = smem_u32(smem);

    const int tid  = threadIdx.x;
    const int wid  = tid >> 5;
    const int lane = tid & 31;

    const int wm  = wid & 1;
    const int wn  = wid >> 1;
    const int grp = lane >> 3;
    const int l7  = lane & 7;
    const int hi  = lane >> 4;

    uint32_t aAddr[4], bAddr[2], cA[4], cB[4];
#pragma unroll
    for (int i = 0; i < 4; ++i)
        aAddr[i] = sm + (uint32_t)(wm * 64 + i * 16 + (lane & 15)) * 128;
#pragma unroll
    for (int h = 0; h < 2; ++h)
        bAddr[h] = sm + A_ST + (uint32_t)(wn * 32 + h * 16 + (grp >> 1) * 8 + l7) * 128;
#pragma unroll
    for (int ks = 0; ks < 4; ++ks) {
        cA[ks] = (uint32_t)(((ks * 2 + hi) ^ l7) * 16);
        cB[ks] = (uint32_t)(((ks * 2 + (grp & 1)) ^ l7) * 16);
    }

    // first tile's stages 0,1 in flight before the tile loop
    {
        int t0   = blockIdx.x;
        int oc0p = (t0 & 1) * 128;
        int m0p  = (t0 >> 1) * 128;
        load_stage(sm, 0, m0p, oc0p, tid);
        load_stage(sm, 1, m0p, oc0p, tid);
    }

    for (int tile = blockIdx.x; tile < NTILES; tile += GRID_P) {
        const int oc0 = (tile & 1) * 128;
        const int m0  = (tile >> 1) * 128;

        float acc[4][4][4];
#pragma unroll
        for (int i = 0; i < 4; ++i)
#pragma unroll
            for (int j = 0; j < 4; ++j)
#pragma unroll
                for (int p = 0; p < 4; ++p) acc[i][j][p] = 0.f;

        cp_wait1();                    // stage 0 resident
        __syncthreads();

        uint32_t aR[4], aN[4], bF[2][4][2];
        {   // prime frags from stage slot 0
            uint32_t r[4];
            ldsm4(r, bAddr[0] + cB[0]); bF[0][0][0]=r[0]; bF[0][0][1]=r[1]; bF[0][1][0]=r[2]; bF[0][1][1]=r[3];
            ldsm4(r, bAddr[1] + cB[0]); bF[0][2][0]=r[0]; bF[0][2][1]=r[1]; bF[0][3][0]=r[2]; bF[0][3][1]=r[3];
            ldsm4(aR, aAddr[0] + cA[0]);
        }

        for (int it = 0; it < KITER; ++it) {
            const uint32_t sb  = (uint32_t)(it % STAGES) * STAGE_B;
            const uint32_t sbN = (uint32_t)((it + 1) % STAGES) * STAGE_B;
            if (it + 2 < KITER) load_stage(sm, it + 2, m0, oc0, tid);

#pragma unroll
            for (int ks = 0; ks < 4; ++ks) {
                const int cur = ks & 1;
                const int nxt = cur ^ 1;
                uint32_t (*bR)[2] = bF[cur];

                ldsm4(aN, aAddr[1] + sb + cA[ks]);
#pragma unroll
                for (int j = 0; j < 4; ++j) mma16816(acc[0][j], aR, bR[j]);
                ldsm4(aR, aAddr[2] + sb + cA[ks]);
#pragma unroll
                for (int j = 0; j < 4; ++j) mma16816(acc[1][j], aN, bR[j]);
                ldsm4(aN, aAddr[3] + sb + cA[ks]);
#pragma unroll
                for (int j = 0; j < 4; ++j) mma16816(acc[2][j], aR, bR[j]);

                if (ks < 3) {
                    uint32_t r[4];
                    ldsm4(r, bAddr[0] + sb + cB[ks + 1]);
                    bF[nxt][0][0]=r[0]; bF[nxt][0][1]=r[1]; bF[nxt][1][0]=r[2]; bF[nxt][1][1]=r[3];
                    ldsm4(r, bAddr[1] + sb + cB[ks + 1]);
                    bF[nxt][2][0]=r[0]; bF[nxt][2][1]=r[1]; bF[nxt][3][0]=r[2]; bF[nxt][3][1]=r[3];
                    ldsm4(aR, aAddr[0] + sb + cA[ks + 1]);
#pragma unroll
                    for (int j = 0; j < 4; ++j) mma16816(acc[3][j], aN, bR[j]);
                } else if (it + 1 < KITER) {
                    if (it < KITER - 3) cp_wait1(); else cp_wait0();
                    uint32_t r[4];
                    ldsm4(r, bAddr[0] + sbN + cB[0]);
                    bF[nxt][0][0]=r[0]; bF[nxt][0][1]=r[1]; bF[nxt][1][0]=r[2]; bF[nxt][1][1]=r[3];
                    ldsm4(r, bAddr[1] + sbN + cB[0]);
                    bF[nxt][2][0]=r[0]; bF[nxt][2][1]=r[1]; bF[nxt][3][0]=r[2]; bF[nxt][3][1]=r[3];
                    ldsm4(aR, aAddr[0] + sbN + cA[0]);
#pragma unroll
                    for (int j = 0; j < 4; ++j) mma16816(acc[3][j], aN, bR[j]);
                    __syncthreads();
                } else {
#pragma unroll
                    for (int j = 0; j < 4; ++j) mma16816(acc[3][j], aN, bR[j]);
                }
            }
        }

        // all warps done reading this tile's smem before reusing slots 0/1
        __syncthreads();

        // overlap next tile's first loads with the epilogue
        const int ntile = tile + GRID_P;
        if (ntile < NTILES) {
            const int noc0 = (ntile & 1) * 128;
            const int nm0  = (ntile >> 1) * 128;
            load_stage(sm, 0, nm0, noc0, tid);
            load_stage(sm, 1, nm0, noc0, tid);
        }

        // epilogue
        const int g  = lane >> 2;
        const int c2 = (lane & 3) * 2;
        const int n  = m0 >> 12;
        float bia[4][2];
#pragma unroll
        for (int j = 0; j < 4; ++j) {
            int oc = oc0 + wn * 32 + j * 8 + c2;
            bia[j][0] = __ldg(bias + oc);
            bia[j][1] = __ldg(bias + oc + 1);
        }
#pragma unroll
        for (int i = 0; i < 4; ++i) {
#pragma unroll
            for (int rr = 0; rr < 2; ++rr) {
                int m = m0 + wm * 64 + i * 16 + g + rr * 8;
                size_t base = (size_t)n * (C_OUT * 4096) + (m & 4095);
#pragma unroll
                for (int j = 0; j < 4; ++j) {
                    int oc = oc0 + wn * 32 + j * 8 + c2;
                    out[base + (size_t)oc * 4096]       = acc[i][j][rr * 2 + 0] + bia[j][0];
                    out[base + (size_t)(oc + 1) * 4096] = acc[i][j][rr * 2 + 1] + bia[j][1];
                }
            }
        }
    }
}

// ---------------------------------------------------------------------------
extern "C" void kernel_launch(void* const* d_in, const int* in_sizes, int n_in,
                              void* d_out, int out_size) {
    const float* x      = (const float*)d_in[0];
    const float* W      = (const float*)d_in[1];
    const float* b      = (const float*)d_in[2];
    const float* lora_A = (const float*)d_in[3];
    const float* lora_B = (const float*)d_in[4];
    float* out = (float*)d_out;

    static int smem_set = 0;
    if (!smem_set) {
        cudaFuncSetAttribute(gemm_kernel,
                             cudaFuncAttributeMaxDynamicSharedMemorySize, SMEM_TOTAL);
        smem_set = 1;
    }

    prologue_kernel<<<1024 + (C_OUT * KDIM) / 256, 256>>>(x, W, lora_A, lora_B);
    gemm_kernel<<<GRID_P, 256, SMEM_TOTAL>>>(b, out);
}